// round 5
// baseline (speedup 1.0000x reference)
#include <cuda_runtime.h>
#include <math.h>

// Problem constants
#define S        2048
#define ROWS     65536            // 2*16*2048 rows of x; also 32*2048 gemm outputs
#define TNB      64               // t-tile per partial-GEMM block
#define KCB      64               // k-chunk per partial-GEMM block
#define KSPLIT   32               // 2048 / KCB

// Scratch (allocation-free rule: __device__ globals)
__device__ int   g_idx[ROWS];
__device__ float g_gather[ROWS];
__device__ float g_part[KSPLIT * ROWS];   // 8 MB fp32 partials [ks][m][t]

// ---------------------------------------------------------------------------
// Kernel A: one WARP per row. Copy x->out (streaming float4) while reducing
// first-occurrence argmax. 8 warps/block, no smem, no __syncthreads.
// Loads batched 8-deep for MLP; __ldcs/__stcs to avoid L2 thrash.
// ---------------------------------------------------------------------------
__global__ void __launch_bounds__(256)
copy_argmax_kernel(const float* __restrict__ x, float* __restrict__ out)
{
    const int warp = threadIdx.x >> 5;
    const int lane = threadIdx.x & 31;
    const int row  = blockIdx.x * 8 + warp;

    const float4* __restrict__ xr = (const float4*)(x + (size_t)row * S);
    float4* __restrict__ orow     = (float4*)(out + (size_t)row * S);

    float best = -INFINITY;
    int   bidx = 0;

    // 512 float4 per row, 16 per lane, processed in 2 batches of 8.
    #pragma unroll
    for (int b = 0; b < 2; b++) {
        float4 v[8];
        #pragma unroll
        for (int i = 0; i < 8; i++)
            v[i] = __ldcs(xr + lane + (b * 8 + i) * 32);
        #pragma unroll
        for (int i = 0; i < 8; i++)
            __stcs(orow + lane + (b * 8 + i) * 32, v[i]);
        #pragma unroll
        for (int i = 0; i < 8; i++) {
            const int base = (lane + (b * 8 + i) * 32) * 4;
            if (v[i].x > best) { best = v[i].x; bidx = base + 0; }
            if (v[i].y > best) { best = v[i].y; bidx = base + 1; }
            if (v[i].z > best) { best = v[i].z; bidx = base + 2; }
            if (v[i].w > best) { best = v[i].w; bidx = base + 3; }
        }
    }

    // Warp reduction, first-occurrence tie-break (smaller index wins ties)
    #pragma unroll
    for (int off = 16; off > 0; off >>= 1) {
        float ov = __shfl_down_sync(0xFFFFFFFFu, best, off);
        int   oi = __shfl_down_sync(0xFFFFFFFFu, bidx, off);
        if (ov > best || (ov == best && oi < bidx)) { best = ov; bidx = oi; }
    }

    if (lane == 0) {
        g_idx[row]    = bidx;
        g_gather[row] = best;
    }
}

// ---------------------------------------------------------------------------
// Kernel B1: k-split partial GEMM. Grid (32, 32) = 1024 blocks, 128 threads.
// Block computes partial C[32][64] over one 64-wide k-chunk.
// Smem tiles k-major so the inner loop is 2x LDS.128 : 16 FMA per thread.
// ---------------------------------------------------------------------------
__global__ void __launch_bounds__(128)
gemm_partial_kernel(const float* __restrict__ W)
{
    __shared__ __align__(16) float gsT[KCB][36];   // [k][m], stride 36 (16B-aligned rows)
    __shared__ __align__(16) float wsT[KCB][68];   // [k][t], stride 68 (16B-aligned rows)

    const int t0  = blockIdx.x * TNB;
    const int k0  = blockIdx.y * KCB;
    const int tid = threadIdx.x;

    // Fill gsT (transposed): thread -> m = tid>>2 (0..31), k-seg (tid&3)*16
    {
        const int m  = tid >> 2;
        const int ks = (tid & 3) * 16;
        #pragma unroll
        for (int j = 0; j < 4; j++) {
            float4 v = *(const float4*)(g_gather + (size_t)m * S + k0 + ks + j * 4);
            gsT[ks + j*4 + 0][m] = v.x;
            gsT[ks + j*4 + 1][m] = v.y;
            gsT[ks + j*4 + 2][m] = v.z;
            gsT[ks + j*4 + 3][m] = v.w;
        }
    }
    // Fill wsT (transposed): thread -> t = tid>>1 (0..63), k-seg (tid&1)*32
    {
        const int t  = tid >> 1;
        const int ks = (tid & 1) * 32;
        #pragma unroll
        for (int j = 0; j < 8; j++) {
            float4 v = *(const float4*)(W + (size_t)(t0 + t) * S + k0 + ks + j * 4);
            wsT[ks + j*4 + 0][t] = v.x;
            wsT[ks + j*4 + 1][t] = v.y;
            wsT[ks + j*4 + 2][t] = v.z;
            wsT[ks + j*4 + 3][t] = v.w;
        }
    }
    __syncthreads();

    const int m0  = (tid & 7) * 4;    // 8 m-groups
    const int tn0 = (tid >> 3) * 4;   // 16 t-groups

    float acc[4][4] = {};

    #pragma unroll 8
    for (int k = 0; k < KCB; k++) {
        const float4 a = *(const float4*)&gsT[k][m0];
        const float4 w = *(const float4*)&wsT[k][tn0];
        acc[0][0] = fmaf(a.x, w.x, acc[0][0]); acc[0][1] = fmaf(a.x, w.y, acc[0][1]);
        acc[0][2] = fmaf(a.x, w.z, acc[0][2]); acc[0][3] = fmaf(a.x, w.w, acc[0][3]);
        acc[1][0] = fmaf(a.y, w.x, acc[1][0]); acc[1][1] = fmaf(a.y, w.y, acc[1][1]);
        acc[1][2] = fmaf(a.y, w.z, acc[1][2]); acc[1][3] = fmaf(a.y, w.w, acc[1][3]);
        acc[2][0] = fmaf(a.z, w.x, acc[2][0]); acc[2][1] = fmaf(a.z, w.y, acc[2][1]);
        acc[2][2] = fmaf(a.z, w.z, acc[2][2]); acc[2][3] = fmaf(a.z, w.w, acc[2][3]);
        acc[3][0] = fmaf(a.w, w.x, acc[3][0]); acc[3][1] = fmaf(a.w, w.y, acc[3][1]);
        acc[3][2] = fmaf(a.w, w.z, acc[3][2]); acc[3][3] = fmaf(a.w, w.w, acc[3][3]);
    }

    float* p = g_part + (size_t)blockIdx.y * ROWS;
    #pragma unroll
    for (int i = 0; i < 4; i++) {
        float4 v = make_float4(acc[i][0], acc[i][1], acc[i][2], acc[i][3]);
        *(float4*)(p + (size_t)(m0 + i) * S + t0 + tn0) = v;
    }
}

// ---------------------------------------------------------------------------
// Kernel B2: reduce KSPLIT partials (fixed order -> deterministic), + bias,
// exact-erf GELU, scatter into out at argmax positions. 65536 threads.
// ---------------------------------------------------------------------------
__global__ void __launch_bounds__(256)
reduce_gelu_scatter_kernel(const float* __restrict__ bias,
                           float* __restrict__ out)
{
    const int r = blockIdx.x * 256 + threadIdx.x;   // 0..65535  (= m*S + t)
    float s = 0.0f;
    #pragma unroll
    for (int ks = 0; ks < KSPLIT; ks++)
        s += g_part[(size_t)ks * ROWS + r];

    const int t = r & (S - 1);
    const float v  = s + bias[t];
    const float ge = 0.5f * v * (1.0f + erff(v * 0.70710678118654752f));
    out[(size_t)r * S + (size_t)g_idx[r]] = ge;
}

// ---------------------------------------------------------------------------
extern "C" void kernel_launch(void* const* d_in, const int* in_sizes, int n_in,
                              void* d_out, int out_size)
{
    const float* x    = (const float*)d_in[0];   // [2,16,2048,2048]
    const float* W    = (const float*)d_in[1];   // [2048,2048]
    const float* bias = (const float*)d_in[2];   // [2048]
    float* out        = (float*)d_out;

    copy_argmax_kernel<<<ROWS / 8, 256>>>(x, out);
    gemm_partial_kernel<<<dim3(S / TNB, KSPLIT), 128>>>(W);
    reduce_gelu_scatter_kernel<<<ROWS / 256, 256>>>(bias, out);
}